// round 12
// baseline (speedup 1.0000x reference)
#include <cuda_runtime.h>
#include <cuda_bf16.h>

// PatchShuffle: T=1024 (16 rows x 64 cols), B=64, C=768, STRIPE_W=48.
// Outputs concatenated as float32:
//   visible       [256*64*768]   gather of shuffled rows 0..255
//   fwd           [1024*64]      forward permutation (as float)
//   bwd           [1024*64]      inverse permutation (as float)
//   stripe_bounds [2*64]         {start, start+48} per batch
//
// perm(b, j):  s = start[b]
//   j <  s        -> j
//   s <= j < 16   -> j + 48
//   j >= 16       -> s + (j-16)
// inverse:
//   col <  s        -> col
//   s <= col < s+48 -> 16 + (col - s)
//   col >= s+48     -> col - 48
//
// PROTECTED (measured):
//  * Visible-gather loop is Round-3's exact issue pattern (per-item idx math +
//    __ldg inside the address chain). The stagger avoids the front-batched-LDG
//    cross-CTA L1tex queue contention that regressed R5/R6 to 21us.
//  * __stcs on bulk stores: evict-first output keeps the 48MB read set
//    L2-resident across warm graph replays (R3 13.0 vs R8 14.8 with default).

#define STRIPE_W   48
#define B_         64
#define C_         768
#define C4_        192
#define T_VIS      256
#define T_ALL      1024

#define N_VIS4     (T_VIS * B_ * C4_)        // 3,145,728 float4 items
#define OFF_FWD    (T_VIS * B_ * C_)         // 12,582,912 floats
#define N_FWD      (T_ALL * B_)              // 65,536
#define OFF_BWD    (OFF_FWD + N_FWD)
#define OFF_SB     (OFF_BWD + N_FWD)

#define ILP        4
#define THREADS    256
#define VIS_BLOCKS (N_VIS4 / (THREADS * ILP))    // 3072 exactly
#define VIS_STRIDE (VIS_BLOCKS * THREADS)        // 786,432
#define N_TAIL     (2 * N_FWD + 128)             // 131,200
#define TAIL_BLOCKS ((N_TAIL + THREADS - 1) / THREADS)  // 513 (folded into grid)

__device__ __forceinline__ int perm_of(int s, int j) {
    return (j < s) ? j : ((j < 16) ? (j + STRIPE_W) : (s + (j - 16)));
}

__device__ __forceinline__ int inv_of(int s, int col) {
    return (col < s) ? col : ((col < s + STRIPE_W) ? (16 + (col - s)) : (col - STRIPE_W));
}

__global__ void __launch_bounds__(THREADS)
patchshuffle_kernel(const float4* __restrict__ patches,
                    const int*    __restrict__ start_cols,
                    float*        __restrict__ out) {
    int bid = blockIdx.x;
    int tid = threadIdx.x;

    // ---- visible gather: R3's exact pattern (4 staggered float4 per thread) ----
    {
        int base = bid * THREADS + tid;
        float4 v[ILP];
        #pragma unroll
        for (int k = 0; k < ILP; k++) {
            int idx  = base + k * VIS_STRIDE;   // always < N_VIS4 (exact fit)
            int c4   = idx % C4_;
            int pair = idx / C4_;               // t*64 + b
            int b    = pair & 63;
            int t    = pair >> 6;               // 0..255
            int row  = t >> 6;                  // 0..3
            int j    = t & 63;
            int s    = __ldg(start_cols + b);
            int p    = perm_of(s, j);
            v[k] = patches[(((row << 6) + p) * B_ + b) * C4_ + c4];
        }
        float4* o4 = reinterpret_cast<float4*>(out);
        #pragma unroll
        for (int k = 0; k < ILP; k++)
            __stcs(o4 + base + k * VIS_STRIDE, v[k]);   // evict-first (protected)
    }

    // ---- tail folded into the first 513 blocks (no straggler wave) ----
    if (bid < TAIL_BLOCKS) {
        int r = bid * THREADS + tid;
        if (r < N_FWD) {
            // fwd[t][b]
            int t   = r >> 6;
            int b   = r & 63;
            int row = t >> 6;
            int j   = t & 63;
            int s   = __ldg(start_cols + b);
            __stcs(out + OFF_FWD + r, (float)((row << 6) + perm_of(s, j)));
            return;
        }
        r -= N_FWD;
        if (r < N_FWD) {
            // bwd[i][b]
            int i   = r >> 6;
            int b   = r & 63;
            int row = i >> 6;
            int col = i & 63;
            int s   = __ldg(start_cols + b);
            __stcs(out + OFF_BWD + r, (float)((row << 6) + inv_of(s, col)));
            return;
        }
        r -= N_FWD;
        if (r < 128) {
            // stripe_bounds[2][64]
            int b = r & 63;
            int s = __ldg(start_cols + b);
            __stcs(out + OFF_SB + r, (float)((r < 64) ? s : (s + STRIPE_W)));
        }
    }
}

extern "C" void kernel_launch(void* const* d_in, const int* in_sizes, int n_in,
                              void* d_out, int out_size) {
    const float4* patches    = (const float4*)d_in[0];
    const int*    start_cols = (const int*)d_in[1];
    float*        out        = (float*)d_out;

    patchshuffle_kernel<<<VIS_BLOCKS, THREADS>>>(patches, start_cols, out);
}

// round 13
// speedup vs baseline: 1.2197x; 1.2197x over previous
#include <cuda_runtime.h>
#include <cuda_bf16.h>

// PatchShuffle: T=1024 (16 rows x 64 cols), B=64, C=768, STRIPE_W=48.
// Outputs concatenated as float32:
//   visible       [256*64*768]   gather of shuffled rows 0..255
//   fwd           [1024*64]      forward permutation (as float)
//   bwd           [1024*64]      inverse permutation (as float)
//   stripe_bounds [2*64]         {start, start+48} per batch
//
// perm(b, j):  s = start[b]
//   j <  s        -> j
//   s <= j < 16   -> j + 48
//   j >= 16       -> s + (j-16)
// inverse:
//   col <  s        -> col
//   s <= col < s+48 -> 16 + (col - s)
//   col >= s+48     -> col - 48
//
// STRATEGY (measured across R3/R5/R6/R8/R9):
//  * Batched LDG.128 bursts regress ONLY at high CTA residency (cross-CTA
//    L1tex-queue contention, spr ~ f(oe * MLP_p1), threshold ~16).
//    Fix: cap occupancy to 2 CTAs/SM by passing 100KB dynamic smem as a pure
//    launch parameter (kernel never touches it). oe*MLP = 2*8 = 16.
//  * __stcs on output: evict-first keeps the 48MB read set L2-resident across
//    warm graph replays (R3 13.0 vs R8 14.8).

#define STRIPE_W   48
#define B_         64
#define C_         768
#define C4_        192
#define T_VIS      256
#define T_ALL      1024

#define N_VIS4     (T_VIS * B_ * C4_)        // 3,145,728 float4
#define OFF_FWD    (T_VIS * B_ * C_)         // 12,582,912 floats
#define N_FWD      (T_ALL * B_)              // 65,536
#define OFF_BWD    (OFF_FWD + N_FWD)
#define OFF_SB     (OFF_BWD + N_FWD)

#define ILP        8
#define THREADS    512
#define VIS_STRIDE (N_VIS4 / ILP)            // 393,216 = 2048*192 (mult of 192 and 64)
#define VIS_BLOCKS (VIS_STRIDE / THREADS)    // 768 exactly
#define SRC_STEP   (64 * B_ * C4_)           // 786,432 float4 per row step (t += 64)

#define N_TAIL     (2 * N_FWD + 128)         // 131,200
#define TAIL_BLOCKS ((N_TAIL + THREADS - 1) / THREADS)  // 257

#define SMEM_CAP   (100 * 1024)              // occupancy limiter: 2 CTAs/SM

__device__ __forceinline__ int perm_of(int s, int j) {
    return (j < s) ? j : ((j < 16) ? (j + STRIPE_W) : (s + (j - 16)));
}

__device__ __forceinline__ int inv_of(int s, int col) {
    return (col < s) ? col : ((col < s + STRIPE_W) ? (16 + (col - s)) : (col - STRIPE_W));
}

__global__ void __launch_bounds__(THREADS)
patchshuffle_kernel(const float4* __restrict__ patches,
                    const int*    __restrict__ start_cols,
                    float*        __restrict__ out) {
    int bid = blockIdx.x;
    int tid = threadIdx.x;

    if (bid < VIS_BLOCKS) {
        // ---- visible gather: flat layout, 8 items/thread, stride 393,216 ----
        // base in [0, 393216): pair0 in [0, 2048) -> b invariant, t0 in [0,32).
        // item m: pair = pair0 + 2048m -> t = t0 + 32m, row = m>>1,
        //         j = t0 (m even) or t0+32 (m odd; always stripe branch).
        int base  = bid * THREADS + tid;
        int c4    = base % C4_;               // invariant across items
        int pair0 = base / C4_;
        int b     = pair0 & 63;               // invariant
        int t0    = pair0 >> 6;               // in [0,32)
        int s     = __ldg(start_cols + b);    // ONE scoreboarded load

        int p_even = perm_of(s, t0);          // j = t0 < 32
        int p_odd  = s + t0 + 16;             // j = t0+32 >= 16 -> stripe branch

        int src_even = (p_even * B_ + b) * C4_ + c4;
        int src_odd  = (p_odd  * B_ + b) * C4_ + c4;

        float4 v[ILP];
        #pragma unroll
        for (int m = 0; m < ILP; m++) {
            int src = ((m & 1) ? src_odd : src_even) + (m >> 1) * SRC_STEP;
            v[m] = patches[src];              // 8 independent LDG.128
        }
        float4* o4 = reinterpret_cast<float4*>(out);
        #pragma unroll
        for (int m = 0; m < ILP; m++)
            __stcs(o4 + base + m * VIS_STRIDE, v[m]);   // evict-first
        return;
    }

    // ---- tail: index outputs ----
    int r = (bid - VIS_BLOCKS) * THREADS + tid;
    if (r < N_FWD) {
        int t   = r >> 6;
        int b   = r & 63;
        int row = t >> 6;
        int j   = t & 63;
        int s   = __ldg(start_cols + b);
        __stcs(out + OFF_FWD + r, (float)((row << 6) + perm_of(s, j)));
        return;
    }
    r -= N_FWD;
    if (r < N_FWD) {
        int i   = r >> 6;
        int b   = r & 63;
        int row = i >> 6;
        int col = i & 63;
        int s   = __ldg(start_cols + b);
        __stcs(out + OFF_BWD + r, (float)((row << 6) + inv_of(s, col)));
        return;
    }
    r -= N_FWD;
    if (r < 128) {
        int b = r & 63;
        int s = __ldg(start_cols + b);
        __stcs(out + OFF_SB + r, (float)((r < 64) ? s : (s + STRIPE_W)));
    }
}

extern "C" void kernel_launch(void* const* d_in, const int* in_sizes, int n_in,
                              void* d_out, int out_size) {
    const float4* patches    = (const float4*)d_in[0];
    const int*    start_cols = (const int*)d_in[1];
    float*        out        = (float*)d_out;

    // Allow >48KB dynamic smem (pure occupancy limiter; kernel ignores it).
    cudaFuncSetAttribute(patchshuffle_kernel,
                         cudaFuncAttributeMaxDynamicSharedMemorySize, SMEM_CAP);

    patchshuffle_kernel<<<VIS_BLOCKS + TAIL_BLOCKS, THREADS, SMEM_CAP>>>(
        patches, start_cols, out);
}

// round 15
// speedup vs baseline: 1.6054x; 1.3162x over previous
#include <cuda_runtime.h>
#include <cuda_bf16.h>

// PatchShuffle: T=1024 (16 rows x 64 cols), B=64, C=768, STRIPE_W=48.
// Outputs concatenated as float32:
//   visible       [256*64*768]   gather of shuffled rows 0..255
//   fwd           [1024*64]      forward permutation (as float)
//   bwd           [1024*64]      inverse permutation (as float)
//   stripe_bounds [2*64]         {start, start+48} per batch
//
// perm(b, j):  s = start[b]
//   j <  s        -> j
//   s <= j < 16   -> j + 48
//   j >= 16       -> s + (j-16)
// inverse:
//   col <  s        -> col
//   s <= col < s+48 -> 16 + (col - s)
//   col >= s+48     -> col - 48
//
// SCHEDULING CONTRACT (measured R3/R5/R6/R9/R12):
//  * Front-batched LDG.128 bursts at full residency hit cross-CTA L1tex-queue
//    contention (21us). Occupancy-capping clears the queue but starves TLP
//    (17us). The winning shape is FULL occupancy + MLP_p1=2.
//  * To force MLP_p1=2 deterministically: `patches`/`out` are NOT __restrict__
//    (possible aliasing), and stores are interleaved between load pairs, so
//    the compiler cannot hoist later loads above earlier stores.
//  * __stcs (evict-first) on output: keeps the 48MB read set L2-resident
//    across warm graph replays (R3 13.0 vs R8 14.8). Protected.

#define STRIPE_W   48
#define B_         64
#define C_         768
#define C4_        192
#define T_VIS      256
#define T_ALL      1024

#define N_VIS4     (T_VIS * B_ * C4_)        // 3,145,728 float4
#define OFF_FWD    (T_VIS * B_ * C_)         // 12,582,912 floats
#define N_FWD      (T_ALL * B_)              // 65,536
#define OFF_BWD    (OFF_FWD + N_FWD)
#define OFF_SB     (OFF_BWD + N_FWD)

#define ILP        4
#define THREADS    256
#define VIS_STRIDE (N_VIS4 / ILP)            // 786,432 = 4096*192
#define VIS_BLOCKS (VIS_STRIDE / THREADS)    // 3072 exactly
#define SRC_STEP   (64 * B_ * C4_)           // 786,432 float4 (t += 64 step)

#define N_TAIL     (2 * N_FWD + 128)         // 131,200
#define TAIL_BLOCKS ((N_TAIL + THREADS - 1) / THREADS)  // 513 (folded)

__device__ __forceinline__ int perm_of(int s, int j) {
    return (j < s) ? j : ((j < 16) ? (j + STRIPE_W) : (s + (j - 16)));
}

__device__ __forceinline__ int inv_of(int s, int col) {
    return (col < s) ? col : ((col < s + STRIPE_W) ? (16 + (col - s)) : (col - STRIPE_W));
}

__global__ void __launch_bounds__(THREADS)
patchshuffle_kernel(const float4* patches,          // intentionally NOT __restrict__
                    const int*    __restrict__ start_cols,
                    float*        out) {            // intentionally NOT __restrict__
    int bid = blockIdx.x;
    int tid = threadIdx.x;

    // ---- visible gather: 4 items/thread at stride 786,432 ----
    // With this stride: c4, b, t0 are invariant across items; item m is
    // simply row=m, so src_m = src0 + m*SRC_STEP and dst_m = base + m*VIS_STRIDE.
    {
        int base  = bid * THREADS + tid;
        int c4    = base % C4_;
        int pair0 = base / C4_;              // in [0, 4096)
        int b     = pair0 & 63;
        int t0    = pair0 >> 6;              // in [0, 64) == j for ALL items
        int s     = __ldg(start_cols + b);
        int p     = perm_of(s, t0);          // computed ONCE

        const float4* src = patches + (p * B_ + b) * C4_ + c4;
        float4*       dst = reinterpret_cast<float4*>(out) + base;

        // Pairwise load/store interleave; aliasing forbids hoisting -> MLP_p1=2.
        float4 v0 = src[0 * SRC_STEP];
        float4 v1 = src[1 * SRC_STEP];
        __stcs(dst + 0 * VIS_STRIDE, v0);
        __stcs(dst + 1 * VIS_STRIDE, v1);
        float4 v2 = src[2 * SRC_STEP];
        float4 v3 = src[3 * SRC_STEP];
        __stcs(dst + 2 * VIS_STRIDE, v2);
        __stcs(dst + 3 * VIS_STRIDE, v3);
    }

    // ---- tail folded into the first 513 blocks ----
    if (bid < TAIL_BLOCKS) {
        int r = bid * THREADS + tid;
        if (r < N_FWD) {
            // fwd[t][b]
            int t   = r >> 6;
            int b   = r & 63;
            int row = t >> 6;
            int j   = t & 63;
            int s   = __ldg(start_cols + b);
            __stcs(out + OFF_FWD + r, (float)((row << 6) + perm_of(s, j)));
            return;
        }
        r -= N_FWD;
        if (r < N_FWD) {
            // bwd[i][b]
            int i   = r >> 6;
            int b   = r & 63;
            int row = i >> 6;
            int col = i & 63;
            int s   = __ldg(start_cols + b);
            __stcs(out + OFF_BWD + r, (float)((row << 6) + inv_of(s, col)));
            return;
        }
        r -= N_FWD;
        if (r < 128) {
            // stripe_bounds[2][64]
            int b = r & 63;
            int s = __ldg(start_cols + b);
            __stcs(out + OFF_SB + r, (float)((r < 64) ? s : (s + STRIPE_W)));
        }
    }
}

extern "C" void kernel_launch(void* const* d_in, const int* in_sizes, int n_in,
                              void* d_out, int out_size) {
    const float4* patches    = (const float4*)d_in[0];
    const int*    start_cols = (const int*)d_in[1];
    float*        out        = (float*)d_out;

    patchshuffle_kernel<<<VIS_BLOCKS, THREADS>>>(patches, start_cols, out);
}